// round 2
// baseline (speedup 1.0000x reference)
#include <cuda_runtime.h>
#include <stdint.h>
#include <math.h>

// ---------------------------------------------------------------------------
// out[b,o] = min_i ( x[b,i] + mask[o,i] ), B=IN=OUT=512
// mask from JAX threefry bernoulli, PARTITIONABLE variant (modern JAX default):
//   k_bern = full 2-word output of threefry((0,42), (0,0))   [foldlike split]
//   bits(n) = o0 ^ o1 of threefry(k_bern, (0, n))            [counter mode]
// ---------------------------------------------------------------------------

#define B_DIM   512
#define IN_DIM  512
#define OUT_DIM 512
#define N_EDGES (OUT_DIM * IN_DIM)

__device__ float g_mask[N_EDGES];

// ---------------- Threefry-2x32 (constexpr-capable) ------------------------
struct TF2 { uint32_t a, b; };

__host__ __device__ constexpr uint32_t rotl32(uint32_t v, int r) {
    return (v << r) | (v >> (32 - r));
}

__host__ __device__ constexpr TF2 tf2x32(uint32_t k0, uint32_t k1,
                                         uint32_t x0, uint32_t x1) {
    uint32_t k2 = k0 ^ k1 ^ 0x1BD11BDAu;
    x0 += k0; x1 += k1;
    // 20 rounds, key injection every 4
    x0 += x1; x1 = rotl32(x1, 13) ^ x0;
    x0 += x1; x1 = rotl32(x1, 15) ^ x0;
    x0 += x1; x1 = rotl32(x1, 26) ^ x0;
    x0 += x1; x1 = rotl32(x1,  6) ^ x0;
    x0 += k1; x1 += k2 + 1u;
    x0 += x1; x1 = rotl32(x1, 17) ^ x0;
    x0 += x1; x1 = rotl32(x1, 29) ^ x0;
    x0 += x1; x1 = rotl32(x1, 16) ^ x0;
    x0 += x1; x1 = rotl32(x1, 24) ^ x0;
    x0 += k2; x1 += k0 + 2u;
    x0 += x1; x1 = rotl32(x1, 13) ^ x0;
    x0 += x1; x1 = rotl32(x1, 15) ^ x0;
    x0 += x1; x1 = rotl32(x1, 26) ^ x0;
    x0 += x1; x1 = rotl32(x1,  6) ^ x0;
    x0 += k0; x1 += k1 + 3u;
    x0 += x1; x1 = rotl32(x1, 17) ^ x0;
    x0 += x1; x1 = rotl32(x1, 29) ^ x0;
    x0 += x1; x1 = rotl32(x1, 16) ^ x0;
    x0 += x1; x1 = rotl32(x1, 24) ^ x0;
    x0 += k1; x1 += k2 + 4u;
    x0 += x1; x1 = rotl32(x1, 13) ^ x0;
    x0 += x1; x1 = rotl32(x1, 15) ^ x0;
    x0 += x1; x1 = rotl32(x1, 26) ^ x0;
    x0 += x1; x1 = rotl32(x1,  6) ^ x0;
    x0 += k2; x1 += k0 + 5u;
    return TF2{x0, x1};
}

// k_bern at compile time: foldlike split of key(42)=(0,42), row 0 = lane (0,0)
constexpr TF2 KB = tf2x32(0u, 42u, 0u, 0u);

// ---------------- mask generation -------------------------------------------
__global__ void mask_kernel(const float* __restrict__ pw) {
    uint32_t n = blockIdx.x * blockDim.x + threadIdx.x;
    if (n >= N_EDGES) return;

    TF2 r = tf2x32(KB.a, KB.b, 0u, n);     // counter (hi=0, lo=n)
    uint32_t bits = r.a ^ r.b;             // 32-bit partitionable output
    float u = __uint_as_float((bits >> 9) | 0x3F800000u) - 1.0f;

    // p = softmax(pw[n,:])[1], computed in fp64 (closer to truth than JAX fp32)
    float2 w = reinterpret_cast<const float2*>(pw)[n];
    float m = fmaxf(w.x, w.y);
    double e0 = exp((double)(w.x - m));
    double e1 = exp((double)(w.y - m));
    double p  = e1 / (e0 + e1);

    // selected edge (u < p) -> choice 1 -> mask 0 ; else mask 1.
    // zero-connection fixup never fires: p in (0.27,0.73) => P(empty row)<1e-70
    g_mask[n] = ((double)u < p) ? 0.0f : 1.0f;
}

// ---------------- out init to +inf (bit pattern) -----------------------------
__global__ void init_kernel(unsigned* __restrict__ out) {
    int i = blockIdx.x * blockDim.x + threadIdx.x;
    out[i] = 0x7F800000u;  // +inf ; all accumulated values are in [0,2)
}

// ---------------- tiled (min,+) matmul ---------------------------------------
// tile: 64 b-rows x 64 o-cols x 64 k ; grid (OUT/64, B/64, IN/64), k-split
// resolved by atomicMin on float-as-uint (all values >= 0).
#define TB 64
#define TO 64
#define TK 64
#define PAD 4

__global__ __launch_bounds__(256) void minplus_kernel(
    const float* __restrict__ x, unsigned* __restrict__ out) {
    __shared__ float xs[TK][TB + PAD];
    __shared__ float ms[TK][TO + PAD];

    const int ob = blockIdx.x * TO;
    const int bb = blockIdx.y * TB;
    const int kb = blockIdx.z * TK;
    const int tid = threadIdx.x;

    const int c4 = (tid & 15) * 4;
#pragma unroll
    for (int pass = 0; pass < 4; ++pass) {
        int r = (tid >> 4) + pass * 16;
        float4 v = *reinterpret_cast<const float4*>(x + (bb + r) * IN_DIM + kb + c4);
        xs[c4 + 0][r] = v.x; xs[c4 + 1][r] = v.y;
        xs[c4 + 2][r] = v.z; xs[c4 + 3][r] = v.w;
        float4 w = *reinterpret_cast<const float4*>(g_mask + (ob + r) * IN_DIM + kb + c4);
        ms[c4 + 0][r] = w.x; ms[c4 + 1][r] = w.y;
        ms[c4 + 2][r] = w.z; ms[c4 + 3][r] = w.w;
    }
    __syncthreads();

    const int o0 = (tid & 15) * 4;
    const int b0 = (tid >> 4) * 4;

    float acc[4][4];
#pragma unroll
    for (int bi = 0; bi < 4; ++bi)
#pragma unroll
        for (int oi = 0; oi < 4; ++oi) acc[bi][oi] = INFINITY;

#pragma unroll 8
    for (int kk = 0; kk < TK; ++kk) {
        float4 xv = *reinterpret_cast<const float4*>(&xs[kk][b0]);
        float4 mv = *reinterpret_cast<const float4*>(&ms[kk][o0]);
        float xr[4] = {xv.x, xv.y, xv.z, xv.w};
        float mr[4] = {mv.x, mv.y, mv.z, mv.w};
#pragma unroll
        for (int bi = 0; bi < 4; ++bi)
#pragma unroll
            for (int oi = 0; oi < 4; ++oi)
                acc[bi][oi] = fminf(acc[bi][oi], xr[bi] + mr[oi]);
    }

#pragma unroll
    for (int bi = 0; bi < 4; ++bi)
#pragma unroll
        for (int oi = 0; oi < 4; ++oi)
            atomicMin(&out[(bb + b0 + bi) * OUT_DIM + (ob + o0 + oi)],
                      __float_as_uint(acc[bi][oi]));
}

// ---------------------------------------------------------------------------
extern "C" void kernel_launch(void* const* d_in, const int* in_sizes, int n_in,
                              void* d_out, int out_size) {
    const float* x  = (const float*)d_in[0];   // [512, 512]
    const float* pw = (const float*)d_in[1];   // [512, 512, 2]
    unsigned* out   = (unsigned*)d_out;        // [512, 512] float bits

    init_kernel<<<(B_DIM * OUT_DIM) / 256, 256>>>(out);
    mask_kernel<<<N_EDGES / 256, 256>>>(pw);
    dim3 grid(OUT_DIM / TO, B_DIM / TB, IN_DIM / TK);
    minplus_kernel<<<grid, 256>>>(x, out);
}